// round 3
// baseline (speedup 1.0000x reference)
#include <cuda_runtime.h>
#include <math.h>

#define BB   8
#define NN   4096
#define KK   20
#define HH   64
#define DOUT 64

#define QPB   64                 // queries per block
#define SPLIT 4                  // threads per query (candidate-range split)
#define TPB   (QPB * SPLIT)      // 256
#define RANGE (NN / SPLIT)       // 1024

// dynamic smem layout (bytes):
//   sx4    float4[4100]            @ 0       (65600)  -- (x,y,z,-xx), +1 pad / 1024
//   A: mv  float[3*QPB*KK]=3840    @ 65600   (15360)  -- merge values
//      mi  int  [3840]             @ 80960   (15360)  -- merge indices
//   B (aliases A after merge):
//      sp  float[HH*8]=512         @ 65600   (2048)   -- folded W1'/bias'
//      se  float[QPB*63]=4032      @ 67648   (16128)  -- edge diffs, pad-63
#define OFF_A   65600
#define OFF_MI  80960
#define OFF_SP  65600
#define OFF_SE  67648
#define SMEM_BYTES 96320

__device__ __forceinline__ void topk_insert(float d, int m,
                                            float (&vals)[KK], int (&idxs)[KK],
                                            float& vmin, int& mslot) {
#pragma unroll
    for (int i = 0; i < KK; i++)
        if (i == mslot) { vals[i] = d; idxs[i] = m; }
    vmin = vals[0]; mslot = 0;
#pragma unroll
    for (int i = 1; i < KK; i++)
        if (vals[i] < vmin) { vmin = vals[i]; mslot = i; }
}

// ---------------------------------------------------------------------------
// Fused KNN + edge-conv(layer1) + BN + ReLU + dual pooling.
// ---------------------------------------------------------------------------
__global__ void __launch_bounds__(TPB, 2) fused_kernel(
    const float* __restrict__ x,
    const float* __restrict__ w1,  const float* __restrict__ b1,
    const float* __restrict__ g1,  const float* __restrict__ beta1,
    const float* __restrict__ rm1, const float* __restrict__ rv1,
    float* __restrict__ m1o, float* __restrict__ m2o)
{
    extern __shared__ char smem[];
    float4* sx4 = reinterpret_cast<float4*>(smem);
    float*  mv  = reinterpret_cast<float*>(smem + OFF_A);
    int*    mi  = reinterpret_cast<int*>(smem + OFF_MI);
    float*  sp  = reinterpret_cast<float*>(smem + OFF_SP);
    float*  se  = reinterpret_cast<float*>(smem + OFF_SE);

    const int tid = threadIdx.x;
    const int b   = blockIdx.y;
    const int n0  = blockIdx.x * QPB;
    const float* xb = x + (size_t)b * 3 * NN;

    // ---- stage point cloud as (x,y,z,-xx), +1 slot pad per 1024 ----
    for (int i = tid; i < NN; i += TPB) {
        const float x0 = xb[i], x1 = xb[NN + i], x2 = xb[2 * NN + i];
        float w = -x0 * x0;
        w = fmaf(-x1, x1, w);
        w = fmaf(-x2, x2, w);
        sx4[i + (i >> 10)] = make_float4(x0, x1, x2, w);
    }
    __syncthreads();

    // ---- phase 1: split top-20 scan ----
    const int q = tid >> 2, s = tid & 3;
    const int n = n0 + q;
    const float4 ctr = sx4[n + (n >> 10)];
    const float a0 = 2.0f * ctr.x, a1 = 2.0f * ctr.y, a2 = 2.0f * ctr.z;

    float vals[KK];
    int   idxs[KK];
#pragma unroll
    for (int i = 0; i < KK; i++) { vals[i] = -INFINITY; idxs[i] = 0; }
    float vmin = -INFINITY;
    int   mslot = 0;

    float2 buf[32];
    int    cnt = 0;
    const int mbase = s * RANGE;
    const float4* base = sx4 + s * (RANGE + 1);

    for (int j0 = 0; j0 < RANGE; j0 += 8) {
        float d[8];
#pragma unroll
        for (int u = 0; u < 8; u++) {
            const float4 p = base[j0 + u];
            float dd = fmaf(a2, p.z, p.w);
            dd = fmaf(a1, p.y, dd);
            dd = fmaf(a0, p.x, dd);
            d[u] = dd;
        }
#pragma unroll
        for (int u = 0; u < 8; u++) {
            if (d[u] > vmin) {
                buf[cnt] = make_float2(d[u], __int_as_float(mbase + j0 + u));
                cnt++;
            }
        }
        if (__any_sync(0xffffffffu, cnt >= 24)) {
            for (int j = 0; j < cnt; j++) {
                const float dd = buf[j].x;
                if (dd > vmin)
                    topk_insert(dd, __float_as_int(buf[j].y), vals, idxs, vmin, mslot);
            }
            cnt = 0;
        }
    }
    for (int j = 0; j < cnt; j++) {
        const float dd = buf[j].x;
        if (dd > vmin)
            topk_insert(dd, __float_as_int(buf[j].y), vals, idxs, vmin, mslot);
    }

    // ---- phase 2: merge 4 partial lists (ascending range order, strict >) ----
    if (s != 0) {
        float* pv = mv + ((s - 1) * QPB + q) * KK;
        int*   pi = mi + ((s - 1) * QPB + q) * KK;
#pragma unroll
        for (int i = 0; i < KK; i++) { pv[i] = vals[i]; pi[i] = idxs[i]; }
    }
    __syncthreads();
    if (s == 0) {
        for (int src = 0; src < 3; src++) {
            const float* pv = mv + (src * QPB + q) * KK;
            const int*   pi = mi + (src * QPB + q) * KK;
#pragma unroll
            for (int i = 0; i < KK; i++) {
                const float dd = pv[i];
                if (dd > vmin) topk_insert(dd, pi[i], vals, idxs, vmin, mslot);
            }
        }
    }
    __syncthreads();   // done reading region A

    // ---- phase 2.5: write edge diffs + folded layer-1 params (region B) ----
    if (s == 0) {
        float* eq = se + q * 63;
#pragma unroll
        for (int k = 0; k < KK; k++) {
            const int m = idxs[k];
            const float4 p = sx4[m + (m >> 10)];
            eq[k * 3 + 0] = p.x - ctr.x;
            eq[k * 3 + 1] = p.y - ctr.y;
            eq[k * 3 + 2] = p.z - ctr.z;
        }
    }
    if (tid < HH) {
        const float sc = __ldg(g1 + tid) * rsqrtf(__ldg(rv1 + tid) + 1e-5f);
#pragma unroll
        for (int c = 0; c < 6; c++) sp[tid * 8 + c] = __ldg(w1 + tid * 6 + c) * sc;
        sp[tid * 8 + 6] = (__ldg(b1 + tid) - __ldg(rm1 + tid)) * sc + __ldg(beta1 + tid);
    }
    __syncthreads();

    // ---- phase 3: layer-1 conv + BN + ReLU + max/mean pool ----
    // remap: thread = (s2 = 16-channel chunk, q2 = query); warp = 32 consec q2
    const int q2 = tid & 63, s2 = tid >> 6;
    const int n2 = n0 + q2;
    const float4 cc = sx4[n2 + (n2 >> 10)];

    float e[3 * KK];
    {
        const float* eq = se + q2 * 63;
#pragma unroll
        for (int i = 0; i < 3 * KK; i++) e[i] = eq[i];
    }

    const size_t ob = (size_t)b * HH * NN + n2;
#pragma unroll 4
    for (int i = 0; i < 16; i++) {
        const int h = s2 * 16 + i;
        const float* w = sp + h * 8;
        const float W0 = w[0], W1 = w[1], W2 = w[2];
        float cd = w[6];
        cd = fmaf(cc.x, w[3], cd);
        cd = fmaf(cc.y, w[4], cd);
        cd = fmaf(cc.z, w[5], cd);

        float mx = -INFINITY, sm = 0.0f;
#pragma unroll
        for (int k = 0; k < KK; k++) {
            float dt = cd;
            dt = fmaf(e[k * 3 + 0], W0, dt);
            dt = fmaf(e[k * 3 + 1], W1, dt);
            dt = fmaf(e[k * 3 + 2], W2, dt);
            dt = fmaxf(dt, 0.0f);
            mx = fmaxf(mx, dt);
            sm += dt;
        }
        m1o[ob + (size_t)h * NN] = mx;
        m2o[ob + (size_t)h * NN] = sm * (1.0f / KK);
    }
}

// ---------------------------------------------------------------------------
// Layer-2 GEMM: out[b,o,n] = ReLU(BN(sum_c w2[o,c]*cat[b,c,n]))
// ---------------------------------------------------------------------------
__global__ void __launch_bounds__(256) edgeB_kernel(
    const float* __restrict__ m1o, const float* __restrict__ m2o,
    const float* __restrict__ w2,  const float* __restrict__ b2,
    const float* __restrict__ g2,  const float* __restrict__ beta2,
    const float* __restrict__ rm2, const float* __restrict__ rv2,
    float* __restrict__ out)
{
    __shared__ float sw[DOUT * 129];
    __shared__ float ssc[DOUT], sbi[DOUT];

    const int tid = threadIdx.x;
    for (int i = tid; i < DOUT * 2 * HH; i += 256) {
        const int o = i >> 7, c = i & 127;
        sw[o * 129 + c] = __ldg(w2 + i);
    }
    if (tid < DOUT) {
        const float sc = __ldg(g2 + tid) * rsqrtf(__ldg(rv2 + tid) + 1e-5f);
        ssc[tid] = sc;
        sbi[tid] = (__ldg(b2 + tid) - __ldg(rm2 + tid)) * sc + __ldg(beta2 + tid);
    }
    __syncthreads();

    const int n4    = tid & 15;
    const int obase = tid >> 4;
    const int b  = blockIdx.y;
    const int n0 = blockIdx.x * 64 + n4 * 4;

    float4 acc[4];
#pragma unroll
    for (int j = 0; j < 4; j++) acc[j] = make_float4(0.f, 0.f, 0.f, 0.f);

    const float* cat0 = m1o + (size_t)b * HH * NN + n0;
    const float* cat1 = m2o + (size_t)b * HH * NN + n0;

#pragma unroll 2
    for (int c = 0; c < HH; c++) {
        const float4 v = __ldg(reinterpret_cast<const float4*>(cat0 + (size_t)c * NN));
#pragma unroll
        for (int j = 0; j < 4; j++) {
            const float w = sw[(obase + 16 * j) * 129 + c];
            acc[j].x = fmaf(w, v.x, acc[j].x);
            acc[j].y = fmaf(w, v.y, acc[j].y);
            acc[j].z = fmaf(w, v.z, acc[j].z);
            acc[j].w = fmaf(w, v.w, acc[j].w);
        }
    }
#pragma unroll 2
    for (int c = 0; c < HH; c++) {
        const float4 v = __ldg(reinterpret_cast<const float4*>(cat1 + (size_t)c * NN));
#pragma unroll
        for (int j = 0; j < 4; j++) {
            const float w = sw[(obase + 16 * j) * 129 + HH + c];
            acc[j].x = fmaf(w, v.x, acc[j].x);
            acc[j].y = fmaf(w, v.y, acc[j].y);
            acc[j].z = fmaf(w, v.z, acc[j].z);
            acc[j].w = fmaf(w, v.w, acc[j].w);
        }
    }

#pragma unroll
    for (int j = 0; j < 4; j++) {
        const int o = obase + 16 * j;
        const float sc = ssc[o], bi = sbi[o];
        float4 r;
        r.x = fmaxf(fmaf(acc[j].x, sc, bi), 0.0f);
        r.y = fmaxf(fmaf(acc[j].y, sc, bi), 0.0f);
        r.z = fmaxf(fmaf(acc[j].z, sc, bi), 0.0f);
        r.w = fmaxf(fmaf(acc[j].w, sc, bi), 0.0f);
        *reinterpret_cast<float4*>(out + ((size_t)b * DOUT + o) * NN + n0) = r;
    }
}

// ---------------------------------------------------------------------------
extern "C" void kernel_launch(void* const* d_in, const int* in_sizes, int n_in,
                              void* d_out, int out_size) {
    const float* x     = (const float*)d_in[0];
    const float* w1    = (const float*)d_in[1];
    const float* b1    = (const float*)d_in[2];
    const float* g1    = (const float*)d_in[3];
    const float* beta1 = (const float*)d_in[4];
    const float* rm1   = (const float*)d_in[5];
    const float* rv1   = (const float*)d_in[6];
    const float* w2    = (const float*)d_in[7];
    const float* b2    = (const float*)d_in[8];
    const float* g2    = (const float*)d_in[9];
    const float* beta2 = (const float*)d_in[10];
    const float* rm2   = (const float*)d_in[11];
    const float* rv2   = (const float*)d_in[12];

    float* out = (float*)d_out;
    float* m1o = out + (size_t)BB * HH * NN;
    float* m2o = m1o + (size_t)BB * HH * NN;

    cudaFuncSetAttribute(fused_kernel,
                         cudaFuncAttributeMaxDynamicSharedMemorySize, SMEM_BYTES);

    fused_kernel<<<dim3(NN / QPB, BB), TPB, SMEM_BYTES>>>(
        x, w1, b1, g1, beta1, rm1, rv1, m1o, m2o);
    edgeB_kernel<<<dim3(NN / 64, BB), 256>>>(m1o, m2o, w2, b2, g2, beta2,
                                             rm2, rv2, out);
}

// round 4
// speedup vs baseline: 1.1355x; 1.1355x over previous
#include <cuda_runtime.h>
#include <math.h>

#define BB   8
#define NN   4096
#define KK   20
#define HH   64
#define DOUT 64

#define QPB   64                 // queries per block
#define SPLIT 4                  // lanes per query (candidate-range split)
#define TPB   (QPB * SPLIT)      // 256
#define RANGE (NN / SPLIT)       // 1024

#define KNN_SMEM ((NN + 4) * 16) // float4[4100] = 65600 B

// scratch for KNN indices (allocation-free rule: __device__ global)
__device__ int g_idx[BB * NN * KK];

__device__ __forceinline__ void topk_insert(float d, int m,
                                            float (&vals)[KK], int (&idxs)[KK],
                                            float& vmin, int& mslot) {
#pragma unroll
    for (int i = 0; i < KK; i++)
        if (i == mslot) { vals[i] = d; idxs[i] = m; }
    vmin = vals[0]; mslot = 0;
#pragma unroll
    for (int i = 1; i < KK; i++)
        if (vals[i] < vmin) { vmin = vals[i]; mslot = i; }
}

// ---------------------------------------------------------------------------
// Kernel 1: brute-force KNN. 4 lanes split the candidate range per query;
// partial top-20 lists merged via register shuffles (no smem, no spills).
// Ranking key: d' = 2*inner(n,m) - xx[m]  (== dist + xx[n], order-equivalent)
// ---------------------------------------------------------------------------
__global__ void __launch_bounds__(TPB) knn_kernel(const float* __restrict__ x) {
    extern __shared__ float4 sx4[];   // (x,y,z,-xx), +1 pad slot per 1024

    const int tid = threadIdx.x;
    const int b   = blockIdx.y;
    const int n0  = blockIdx.x * QPB;
    const float* xb = x + (size_t)b * 3 * NN;

    for (int i = tid; i < NN; i += TPB) {
        const float x0 = xb[i], x1 = xb[NN + i], x2 = xb[2 * NN + i];
        float w = -x0 * x0;
        w = fmaf(-x1, x1, w);
        w = fmaf(-x2, x2, w);
        sx4[i + (i >> 10)] = make_float4(x0, x1, x2, w);
    }
    __syncthreads();

    const int q = tid >> 2, s = tid & 3;
    const int n = n0 + q;
    const float4 ctr = sx4[n + (n >> 10)];
    const float a0 = 2.0f * ctr.x, a1 = 2.0f * ctr.y, a2 = 2.0f * ctr.z;

    float vals[KK];
    int   idxs[KK];
#pragma unroll
    for (int i = 0; i < KK; i++) { vals[i] = -INFINITY; idxs[i] = 0; }
    float vmin = -INFINITY;
    int   mslot = 0;

    float2 buf[32];   // local-mem candidate buffer (predicated push, no diverge)
    int    cnt = 0;
    const int mbase = s * RANGE;
    const float4* base = sx4 + s * (RANGE + 1);

    for (int j0 = 0; j0 < RANGE; j0 += 8) {
        float d[8];
#pragma unroll
        for (int u = 0; u < 8; u++) {
            const float4 p = base[j0 + u];
            float dd = fmaf(a2, p.z, p.w);
            dd = fmaf(a1, p.y, dd);
            dd = fmaf(a0, p.x, dd);
            d[u] = dd;
        }
#pragma unroll
        for (int u = 0; u < 8; u++) {
            if (d[u] > vmin) {
                buf[cnt] = make_float2(d[u], __int_as_float(mbase + j0 + u));
                cnt++;
            }
        }
        if (__any_sync(0xffffffffu, cnt >= 24)) {
            for (int j = 0; j < cnt; j++) {
                const float dd = buf[j].x;
                if (dd > vmin)
                    topk_insert(dd, __float_as_int(buf[j].y), vals, idxs, vmin, mslot);
            }
            cnt = 0;
        }
    }
    for (int j = 0; j < cnt; j++) {
        const float dd = buf[j].x;
        if (dd > vmin)
            topk_insert(dd, __float_as_int(buf[j].y), vals, idxs, vmin, mslot);
    }

    // ---- shuffle-tree merge: s0<-s1, s2<-s3, then s0<-s2.
    // Strict '>' + lower-range-receives keeps lowest index on exact ties.
#pragma unroll
    for (int i = 0; i < KK; i++) {
        const float rv = __shfl_down_sync(0xffffffffu, vals[i], 1);
        const int   ri = __shfl_down_sync(0xffffffffu, idxs[i], 1);
        if ((s & 1) == 0 && rv > vmin)
            topk_insert(rv, ri, vals, idxs, vmin, mslot);
    }
#pragma unroll
    for (int i = 0; i < KK; i++) {
        const float rv = __shfl_down_sync(0xffffffffu, vals[i], 2);
        const int   ri = __shfl_down_sync(0xffffffffu, idxs[i], 2);
        if (s == 0 && rv > vmin)
            topk_insert(rv, ri, vals, idxs, vmin, mslot);
    }

    if (s == 0) {
        int* op = g_idx + ((size_t)b * NN + n) * KK;
#pragma unroll
        for (int i = 0; i < KK; i++) op[i] = idxs[i];
    }
}

// ---------------------------------------------------------------------------
// Kernel 2a: layer-1 (edge conv + BN + ReLU) + dual pooling.
// Thread = point, channel = loop -> coalesced m1/m2 stores, edge diffs in regs.
// ---------------------------------------------------------------------------
__global__ void __launch_bounds__(128) edgeA_kernel(
    const float* __restrict__ x,
    const float* __restrict__ w1,  const float* __restrict__ b1,
    const float* __restrict__ g1,  const float* __restrict__ beta1,
    const float* __restrict__ rm1, const float* __restrict__ rv1,
    float* __restrict__ m1o, float* __restrict__ m2o)
{
    __shared__ float sp[HH][8];   // W'*6, bias', pad

    const int tid = threadIdx.x;
    const int b = blockIdx.y;
    const int n = blockIdx.x * 128 + tid;

    if (tid < HH) {
        const float sc = __ldg(g1 + tid) * rsqrtf(__ldg(rv1 + tid) + 1e-5f);
#pragma unroll
        for (int c = 0; c < 6; c++) sp[tid][c] = __ldg(w1 + tid * 6 + c) * sc;
        sp[tid][6] = (__ldg(b1 + tid) - __ldg(rm1 + tid)) * sc + __ldg(beta1 + tid);
    }
    __syncthreads();

    const float* xb = x + (size_t)b * 3 * NN;
    const float c0 = xb[n];
    const float c1 = xb[NN + n];
    const float c2 = xb[2 * NN + n];

    const int* ip = g_idx + ((size_t)b * NN + n) * KK;
    float e0[KK], e1[KK], e2[KK];
#pragma unroll
    for (int k = 0; k < KK; k++) {
        const int m = __ldg(ip + k);
        e0[k] = __ldg(xb + m) - c0;
        e1[k] = __ldg(xb + NN + m) - c1;
        e2[k] = __ldg(xb + 2 * NN + m) - c2;
    }

    const size_t ob = (size_t)b * HH * NN + n;
#pragma unroll 2
    for (int h = 0; h < HH; h++) {
        const float W0 = sp[h][0], W1 = sp[h][1], W2 = sp[h][2];
        const float W3 = sp[h][3], W4 = sp[h][4], W5 = sp[h][5];
        float cd = sp[h][6];
        cd = fmaf(c0, W3, cd);
        cd = fmaf(c1, W4, cd);
        cd = fmaf(c2, W5, cd);

        float mx = -INFINITY, sm = 0.0f;
#pragma unroll
        for (int k = 0; k < KK; k++) {
            float dt = cd;
            dt = fmaf(e0[k], W0, dt);
            dt = fmaf(e1[k], W1, dt);
            dt = fmaf(e2[k], W2, dt);
            dt = fmaxf(dt, 0.0f);
            mx = fmaxf(mx, dt);
            sm += dt;
        }
        m1o[ob + (size_t)h * NN] = mx;
        m2o[ob + (size_t)h * NN] = sm * (1.0f / KK);
    }
}

// ---------------------------------------------------------------------------
// Kernel 2b: layer-2 GEMM: out[b,o,n] = ReLU(BN(sum_c w2[o,c]*cat[b,c,n]))
// 512 threads: 16 float4 n-groups x 32 o-bases, 2 outputs/thread -> 86% occ.
// ---------------------------------------------------------------------------
__global__ void __launch_bounds__(512) edgeB_kernel(
    const float* __restrict__ m1o, const float* __restrict__ m2o,
    const float* __restrict__ w2,  const float* __restrict__ b2,
    const float* __restrict__ g2,  const float* __restrict__ beta2,
    const float* __restrict__ rm2, const float* __restrict__ rv2,
    float* __restrict__ out)
{
    __shared__ float sw[DOUT * 129];   // [o][c] padded rows
    __shared__ float ssc[DOUT], sbi[DOUT];

    const int tid = threadIdx.x;
    for (int i = tid; i < DOUT * 2 * HH; i += 512) {
        const int o = i >> 7, c = i & 127;
        sw[o * 129 + c] = __ldg(w2 + i);
    }
    if (tid < DOUT) {
        const float sc = __ldg(g2 + tid) * rsqrtf(__ldg(rv2 + tid) + 1e-5f);
        ssc[tid] = sc;
        sbi[tid] = (__ldg(b2 + tid) - __ldg(rm2 + tid)) * sc + __ldg(beta2 + tid);
    }
    __syncthreads();

    const int n4    = tid & 15;        // 16 float4 groups -> 64 n per block
    const int obase = tid >> 4;        // 0..31, thread covers o = obase+32j
    const int b  = blockIdx.y;
    const int n0 = blockIdx.x * 64 + n4 * 4;

    float4 acc[2];
#pragma unroll
    for (int j = 0; j < 2; j++) acc[j] = make_float4(0.f, 0.f, 0.f, 0.f);

    const float* cat0 = m1o + (size_t)b * HH * NN + n0;
    const float* cat1 = m2o + (size_t)b * HH * NN + n0;

#pragma unroll 4
    for (int c = 0; c < HH; c++) {
        const float4 v = __ldg(reinterpret_cast<const float4*>(cat0 + (size_t)c * NN));
#pragma unroll
        for (int j = 0; j < 2; j++) {
            const float w = sw[(obase + 32 * j) * 129 + c];
            acc[j].x = fmaf(w, v.x, acc[j].x);
            acc[j].y = fmaf(w, v.y, acc[j].y);
            acc[j].z = fmaf(w, v.z, acc[j].z);
            acc[j].w = fmaf(w, v.w, acc[j].w);
        }
    }
#pragma unroll 4
    for (int c = 0; c < HH; c++) {
        const float4 v = __ldg(reinterpret_cast<const float4*>(cat1 + (size_t)c * NN));
#pragma unroll
        for (int j = 0; j < 2; j++) {
            const float w = sw[(obase + 32 * j) * 129 + HH + c];
            acc[j].x = fmaf(w, v.x, acc[j].x);
            acc[j].y = fmaf(w, v.y, acc[j].y);
            acc[j].z = fmaf(w, v.z, acc[j].z);
            acc[j].w = fmaf(w, v.w, acc[j].w);
        }
    }

#pragma unroll
    for (int j = 0; j < 2; j++) {
        const int o = obase + 32 * j;
        const float sc = ssc[o], bi = sbi[o];
        float4 r;
        r.x = fmaxf(fmaf(acc[j].x, sc, bi), 0.0f);
        r.y = fmaxf(fmaf(acc[j].y, sc, bi), 0.0f);
        r.z = fmaxf(fmaf(acc[j].z, sc, bi), 0.0f);
        r.w = fmaxf(fmaf(acc[j].w, sc, bi), 0.0f);
        *reinterpret_cast<float4*>(out + ((size_t)b * DOUT + o) * NN + n0) = r;
    }
}

// ---------------------------------------------------------------------------
extern "C" void kernel_launch(void* const* d_in, const int* in_sizes, int n_in,
                              void* d_out, int out_size) {
    const float* x     = (const float*)d_in[0];
    const float* w1    = (const float*)d_in[1];
    const float* b1    = (const float*)d_in[2];
    const float* g1    = (const float*)d_in[3];
    const float* beta1 = (const float*)d_in[4];
    const float* rm1   = (const float*)d_in[5];
    const float* rv1   = (const float*)d_in[6];
    const float* w2    = (const float*)d_in[7];
    const float* b2    = (const float*)d_in[8];
    const float* g2    = (const float*)d_in[9];
    const float* beta2 = (const float*)d_in[10];
    const float* rm2   = (const float*)d_in[11];
    const float* rv2   = (const float*)d_in[12];

    float* out = (float*)d_out;
    float* m1o = out + (size_t)BB * HH * NN;
    float* m2o = m1o + (size_t)BB * HH * NN;

    cudaFuncSetAttribute(knn_kernel,
                         cudaFuncAttributeMaxDynamicSharedMemorySize, KNN_SMEM);

    knn_kernel<<<dim3(NN / QPB, BB), TPB, KNN_SMEM>>>(x);
    edgeA_kernel<<<dim3(NN / 128, BB), 128>>>(x, w1, b1, g1, beta1, rm1, rv1,
                                              m1o, m2o);
    edgeB_kernel<<<dim3(NN / 64, BB), 512>>>(m1o, m2o, w2, b2, g2, beta2,
                                             rm2, rv2, out);
}